// round 17
// baseline (speedup 1.0000x reference)
#include <cuda_runtime.h>
#include <cuda_fp16.h>
#include <cstdint>

#define N_ 4
#define CI_ 64
#define CO_ 64
#define L_ 1024
#define V_ 25
#define P_ 3
#define KW_ 9
#define LT_ 4

// ---------------- scratch (__device__ globals) ----------------
__device__ __align__(16) __half g_u2h[N_*L_*64*32]; // [n][l][c64][w32] pre-BN (fp16)
__device__ __align__(16) __half g_W2h[64*200];      // [c64][200k]
__device__ __align__(16) __half g_Aeh[96*40];       // [(p,v)96][40w]
__device__ __align__(16) __half g_bf2h[64*34];      // [c64][34w]
__device__ float g_sum[CO_], g_sumsq[CO_];

// ---------------- PTX primitives ----------------
__device__ __forceinline__ uint32_t smem_u32(const void* p) {
    uint32_t a;
    asm("{ .reg .u64 t; cvta.to.shared.u64 t, %1; cvt.u32.u64 %0, t; }" : "=r"(a) : "l"(p));
    return a;
}
#define LDSM4(r, addr) \
    asm volatile("ldmatrix.sync.aligned.m8n8.x4.shared.b16 {%0,%1,%2,%3}, [%4];" \
        : "=r"((r)[0]), "=r"((r)[1]), "=r"((r)[2]), "=r"((r)[3]) : "r"(addr))
#define LDSM4T(r, addr) \
    asm volatile("ldmatrix.sync.aligned.m8n8.x4.trans.shared.b16 {%0,%1,%2,%3}, [%4];" \
        : "=r"((r)[0]), "=r"((r)[1]), "=r"((r)[2]), "=r"((r)[3]) : "r"(addr))
#define MMA16816(d, a, b0, b1) \
    asm volatile("mma.sync.aligned.m16n8k16.row.col.f32.f16.f16.f32 " \
        "{%0,%1,%2,%3}, {%4,%5,%6,%7}, {%8,%9}, {%0,%1,%2,%3};" \
        : "+f"((d)[0]), "+f"((d)[1]), "+f"((d)[2]), "+f"((d)[3]) \
        : "r"((a)[0]), "r"((a)[1]), "r"((a)[2]), "r"((a)[3]), "r"(b0), "r"(b1))

// ---------------- k0: fold weights into fp16 / final layouts ----------------
__global__ void k0_prep(const float* __restrict__ A, const float* __restrict__ edge,
                        const float* __restrict__ cw, const float* __restrict__ cb) {
    int tid = threadIdx.x + blockIdx.x * blockDim.x;
    int nth = blockDim.x * gridDim.x;
    for (int i = tid; i < 64*200; i += nth) {
        int c = i / 200, k = i % 200;
        float val = 0.f;
        if (k < 192) { int p = k >> 6, ci = k & 63; val = cw[(p*CO_ + c)*CI_ + ci]; }
        g_W2h[i] = __float2half(val);
    }
    for (int i = tid; i < 96*40; i += nth) {
        int row = i / 40, w = i % 40, p = row >> 5, v = row & 31;
        float val = 0.f;
        if (v < V_ && w < V_) { int j = (p*V_ + v)*V_ + w; val = A[j]*edge[j]; }
        g_Aeh[i] = __float2half(val);
    }
    for (int i = tid; i < 64*34; i += nth) {
        int c = i / 34, w = i % 34;
        float s = 0.f;
        if (w < V_)
            for (int p = 0; p < P_; p++) {
                float col = 0.f;
                for (int v = 0; v < V_; v++) { int j = (p*V_+v)*V_+w; col += A[j]*edge[j]; }
                s += cb[p*CO_ + c]*col;
            }
        g_bf2h[i] = __float2half(s);
    }
    if (tid < CO_) { g_sum[tid] = 0.f; g_sumsq[tid] = 0.f; }
}

// ---------------- k2: pipelined presum + double fp16 GEMM ----------------
// byte offsets
#define SB_XS 0                         // half [256(lt,ci)][40v]   20480
#define SB_T0 20480                     // half [192k][40w]         15360
#define SB_T1 35840                     // half [192k][40w]         15360
#define SB_AE 51200                     // half [96(p,v)][40w]       7680
#define SB_U  58880                     // half [2buf][64c][34w]     8704
#define SB_BF 67584                     // half [64c][34w]           4352
#define SB_ST 71936                     // f32 stats 128              512
#define SB_TOTAL 72448                  // 70.75 KB -> 3 blocks/SM
// W2 staging (transient): [0, 25600)

__global__ void __launch_bounds__(256, 3) k2_fused(const float* __restrict__ x) {
    extern __shared__ char sm[];
    const uint32_t sbase = smem_u32(sm);
    int tid = threadIdx.x, ww = tid >> 5, lane = tid & 31;
    int n = blockIdx.y, l0 = blockIdx.x * LT_;
    const int group = lane >> 2, tq = lane & 3;

    const uint32_t ldsm40  = ((lane & 7) + ((lane >> 3) & 1) * 8) * 80
                           + ((lane >> 4) & 1) * 16;
    const uint32_t ldsm200 = ((lane & 7) + ((lane >> 3) & 1) * 8) * 400
                           + ((lane >> 4) & 1) * 16;

    // ---- phase 0: stage W2 transiently; copy BF; zero stats ----
    {
        const float4* wsrc = (const float4*)g_W2h;
        float4* wdst = (float4*)sm;
        for (int i = tid; i < 3200; i += 256) wdst[i] = wsrc[i];
        const float4* bsrc = (const float4*)g_bf2h;
        float4* bdst = (float4*)(sm + SB_BF);
        for (int i = tid; i < 272; i += 256) bdst[i] = bsrc[i];
        float* st = (float*)(sm + SB_ST);
        if (tid < 128) st[tid] = 0.f;
    }
    __syncthreads();

    // ---- phase 1: cache stage-2 A fragments (6 per warp, kh split) ----
    const int r_s2 = ww & 3;
    const int kh   = ww >> 2;              // 0 or 1
    uint32_t wf[6][4];
    #pragma unroll
    for (int i = 0; i < 6; i++)
        LDSM4(wf[i], sbase + (uint32_t)((r_s2*16)*200 + (kh*6 + i)*16)*2 + ldsm200);
    __syncthreads();

    // ---- phase 2: AE copy + fused temporal presum -> XS ----
    {
        const float4* asrc = (const float4*)g_Aeh;
        float4* adst = (float4*)(sm + SB_AE);
        for (int i = tid; i < 480; i += 256) adst[i] = asrc[i];
    }
    __half* xs = (__half*)(sm + SB_XS);
    for (int it = 0; it < 8; it++) {
        int pair = tid + it*256;
        int ci = pair >> 5, v = pair & 31;
        if (v >= V_) {
            #pragma unroll
            for (int j = 0; j < LT_; j++) xs[(j*64 + ci)*40 + v] = __float2half(0.f);
            continue;
        }
        const float* xb = x + ((size_t)(n*CI_ + ci)*L_)*V_ + v;
        float vals[KW_ - 1 + LT_];
        #pragma unroll
        for (int i = 0; i < KW_ - 1 + LT_; i++) {
            int l = l0 - (KW_ - 1) + i;
            vals[i] = (l >= 0) ? xb[(size_t)l*V_] : 0.f;
        }
        float s = 0.f;
        #pragma unroll
        for (int i = 0; i < KW_ - 1; i++) s += vals[i];
        #pragma unroll
        for (int j = 0; j < LT_; j++) {
            s += vals[j + KW_ - 1];
            xs[(j*64 + ci)*40 + v] = __float2half(s);
            s -= vals[j];
        }
    }
    __syncthreads();

    // stage-1 worker: compute T tiles for lt into buffer buf
    const int ct = ww & 3, hh = ww >> 2;
    auto stage1 = [&](int lt, int buf) {
        uint32_t tb = SB_T0 + (uint32_t)buf * 15360;
        uint32_t a[2][4];
        #pragma unroll
        for (int ks = 0; ks < 2; ks++)
            LDSM4(a[ks], sbase + SB_XS
                  + (uint32_t)((lt*64 + ct*16)*40 + ks*16)*2 + ldsm40);
        #pragma unroll
        for (int q = 0; q < 3; q++) {
            int idx = hh*3 + q, p = idx >> 1, wt = idx & 1;
            float d[2][4] = {{0.f,0.f,0.f,0.f},{0.f,0.f,0.f,0.f}};
            #pragma unroll
            for (int ks = 0; ks < 2; ks++) {
                uint32_t b[4];
                LDSM4T(b, sbase + SB_AE
                       + (uint32_t)((p*32 + ks*16)*40 + wt*16)*2 + ldsm40);
                MMA16816(d[0], a[ks], b[0], b[1]);
                MMA16816(d[1], a[ks], b[2], b[3]);
            }
            #pragma unroll
            for (int j = 0; j < 2; j++) {
                int wcol = wt*16 + j*8 + tq*2;
                int row  = p*64 + ct*16 + group;
                *(__half2*)(sm + tb + (row*40 + wcol)*2)
                    = __floats2half2_rn(d[j][0], d[j][1]);
                *(__half2*)(sm + tb + ((row + 8)*40 + wcol)*2)
                    = __floats2half2_rn(d[j][2], d[j][3]);
            }
        }
    };

    // prologue
    stage1(0, 0);
    __syncthreads();

    const int c0g = r_s2*16 + group;
    float cs0 = 0.f, cs1 = 0.f, cq0 = 0.f, cq1 = 0.f;   // kh1 stats (c0g, c0g+8)

    for (int i = 0; i < LT_; i++) {
        if (i < 3) stage1(i + 1, (i + 1) & 1);

        // ---- stage 2 (partial K per kh) ----
        float e[4][4] = {{0.f,0.f,0.f,0.f},{0.f,0.f,0.f,0.f},
                         {0.f,0.f,0.f,0.f},{0.f,0.f,0.f,0.f}};
        {
            uint32_t tcur = SB_T0 + (uint32_t)(i & 1) * 15360;
            #pragma unroll
            for (int s = 0; s < 6; s++) {
                uint32_t b0[4], b1[4];
                uint32_t tb = sbase + tcur + (uint32_t)(((kh*6 + s)*16)*40)*2 + ldsm40;
                LDSM4T(b0, tb);
                LDSM4T(b1, tb + 32);
                MMA16816(e[0], wf[s], b0[0], b0[1]);
                MMA16816(e[1], wf[s], b0[2], b0[3]);
                MMA16816(e[2], wf[s], b1[0], b1[1]);
                MMA16816(e[3], wf[s], b1[2], b1[3]);
            }
        }
        if (kh == 0) {       // store partial to U[i&1] as fp16
            __half* U = (__half*)(sm + SB_U) + (i & 1) * 2176;
            #pragma unroll
            for (int j = 0; j < 4; j++) {
                int w0 = j*8 + tq*2;
                *(__half2*)(U + c0g*34 + w0)       = __floats2half2_rn(e[j][0], e[j][1]);
                *(__half2*)(U + (c0g + 8)*34 + w0) = __floats2half2_rn(e[j][2], e[j][3]);
            }
        }
        __syncthreads();

        // ---- epilogue (kh1 warps only, register-resident) ----
        if (kh == 1) {
            int l = l0 + i;
            float cnt = (float)((l + 1 < KW_) ? (l + 1) : KW_);
            const __half* U = (const __half*)(sm + SB_U) + (i & 1) * 2176;
            const __half* BF = (const __half*)(sm + SB_BF);
            __half* ug = g_u2h + ((size_t)(n*L_ + l) << 11);   // *2048
            #pragma unroll
            for (int j = 0; j < 4; j++) {
                int w0 = j*8 + tq*2;
                float2 u0 = __half22float2(*(const __half2*)(U + c0g*34 + w0));
                float2 u1 = __half22float2(*(const __half2*)(U + (c0g + 8)*34 + w0));
                float2 b0 = __half22float2(*(const __half2*)(BF + c0g*34 + w0));
                float2 b1 = __half22float2(*(const __half2*)(BF + (c0g + 8)*34 + w0));
                float v00 = e[j][0] + u0.x + cnt*b0.x;
                float v01 = e[j][1] + u0.y + cnt*b0.y;
                float v10 = e[j][2] + u1.x + cnt*b1.x;
                float v11 = e[j][3] + u1.y + cnt*b1.y;
                cs0 += v00 + v01;  cq0 += v00*v00 + v01*v01;
                cs1 += v10 + v11;  cq1 += v10*v10 + v11*v11;
                if (w0 < 26) {
                    *(__half2*)(ug + (c0g << 5) + w0)       = __floats2half2_rn(v00, v01);
                    *(__half2*)(ug + ((c0g + 8) << 5) + w0) = __floats2half2_rn(v10, v11);
                }
            }
        }
        // no trailing barrier: next iter's stage1 writes T[(i+1)&1] (done being
        // read), next stage2 writes U[(i+1)&1] (not the buffer epilogue reads).
    }

    // ---- stats: kh1 quad-reduce then smem atomics, then global ----
    if (kh == 1) {
        #pragma unroll
        for (int s = 1; s <= 2; s <<= 1) {
            cs0 += __shfl_xor_sync(0xffffffff, cs0, s);
            cq0 += __shfl_xor_sync(0xffffffff, cq0, s);
            cs1 += __shfl_xor_sync(0xffffffff, cs1, s);
            cq1 += __shfl_xor_sync(0xffffffff, cq1, s);
        }
        float* st = (float*)(sm + SB_ST);
        if (tq == 0) {
            atomicAdd(&st[c0g], cs0);      atomicAdd(&st[64 + c0g], cq0);
            atomicAdd(&st[c0g + 8], cs1);  atomicAdd(&st[64 + c0g + 8], cq1);
        }
    }
    __syncthreads();
    if (tid < CO_) {
        float* st = (float*)(sm + SB_ST);
        atomicAdd(&g_sum[tid],   st[tid]);
        atomicAdd(&g_sumsq[tid], st[64 + tid]);
    }
}

// ---------------- k4: stats finalize + transpose + BN + relu + residual + relu ----
#define K4_SMEM (208*65*4)
__global__ void __launch_bounds__(512) k4_out(const float* __restrict__ x,
                                              const float* __restrict__ gamma,
                                              const float* __restrict__ beta,
                                              float* __restrict__ out) {
    extern __shared__ float sm4[];
    __shared__ float s_sc[64], s_sh[64];
    int tid = threadIdx.x;
    int n = blockIdx.y, l0 = blockIdx.x * 8;

    if (tid < CO_) {
        const float cnt = (float)(N_*L_*V_);
        float mean = g_sum[tid] / cnt;
        float var  = g_sumsq[tid] / cnt - mean*mean;
        float inv  = rsqrtf(var + 1e-5f);
        float sc   = gamma[tid]*inv;
        s_sc[tid] = sc;
        s_sh[tid] = beta[tid] - mean*sc;
    }

    {   // load fp16 u2 [l][c][32] -> fp32 smem [208 rows=(l*26+w)][ld 65]
        const __half* base = g_u2h + ((size_t)(n*L_ + l0) << 11);
        #pragma unroll
        for (int k = 0; k < 16; k++) {
            int i2 = tid + k*512;            // 8192 half2
            int l = i2 >> 10, c = (i2 >> 4) & 63, wp = i2 & 15;
            if (wp < 13) {
                float2 f = __half22float2(
                    *(const __half2*)(base + (i2 << 1)));
                int row = l*26 + wp*2;
                sm4[row*65 + c]     = f.x;
                sm4[(row + 1)*65 + c] = f.y;
            }
        }
    }
    __syncthreads();

    {   // fixed channel per thread, fully unrolled
        int c = tid >> 3, rg = tid & 7;
        float sc = s_sc[c], sh = s_sh[c];
        const float* xc = x   + ((size_t)(n*CO_ + c)*L_ + l0)*V_;
        float*       oc = out + ((size_t)(n*CO_ + c)*L_ + l0)*V_;
        float xv[V_];
        #pragma unroll
        for (int i = 0; i < V_; i++) xv[i] = xc[i*8 + rg];
        #pragma unroll
        for (int i = 0; i < V_; i++) {
            int rr = i*8 + rg;
            int row = rr + ((rr*41) >> 10);      // rr + rr/25
            float val = sm4[row*65 + c]*sc + sh;
            oc[rr] = fmaxf(fmaxf(val, 0.f) + xv[i], 0.f);
        }
    }
}

// ---------------- launch ----------------
extern "C" void kernel_launch(void* const* d_in, const int* in_sizes, int n_in,
                              void* d_out, int out_size) {
    const float* x     = (const float*)d_in[0];
    const float* A     = (const float*)d_in[1];
    const float* edge  = (const float*)d_in[2];
    const float* cw    = (const float*)d_in[3];
    const float* cb    = (const float*)d_in[4];
    const float* gamma = (const float*)d_in[5];
    const float* beta  = (const float*)d_in[6];
    float* out = (float*)d_out;

    cudaFuncSetAttribute(k2_fused, cudaFuncAttributeMaxDynamicSharedMemorySize, SB_TOTAL);
    cudaFuncSetAttribute(k4_out,   cudaFuncAttributeMaxDynamicSharedMemorySize, K4_SMEM);

    k0_prep<<<80, 256>>>(A, edge, cw, cb);
    k2_fused<<<dim3(L_/LT_, N_), 256, SB_TOTAL>>>(x);
    k4_out<<<dim3(L_/8, N_), 512, K4_SMEM>>>(x, gamma, beta, out);
}